// round 13
// baseline (speedup 1.0000x reference)
#include <cuda_runtime.h>
#include <cstdint>
#include <cstddef>

#define BATCH 128
#define SEQ   1024
#define DIN   512
#define HID   512

// xp[s][b][h] scratch: 1024*128*512 fp32 = 256MB (device global — allocation-free)
__device__ float g_xp[SEQ * BATCH * HID];

typedef unsigned long long ull;
static __device__ __forceinline__ ull dup2(float a) {
    ull r; asm("mov.b64 %0, {%1, %1};" : "=l"(r) : "f"(a)); return r;
}
static __device__ __forceinline__ ull pack2(float a, float b) {
    ull r; asm("mov.b64 %0, {%1, %2};" : "=l"(r) : "f"(a), "f"(b)); return r;
}
static __device__ __forceinline__ void unpack2(ull v, float& lo, float& hi) {
    asm("mov.b64 {%0, %1}, %2;" : "=f"(lo), "=f"(hi) : "l"(v));
}
static __device__ __forceinline__ void fma2(ull& acc, ull a, ull b) {
    asm("fma.rn.f32x2 %0, %1, %2, %0;" : "+l"(acc) : "l"(a), "l"(b));
}
static __device__ __forceinline__ ull add2v(ull a, ull b) {
    ull r; asm("add.rn.f32x2 %0, %1, %2;" : "=l"(r) : "l"(a), "l"(b)); return r;
}
static __device__ __forceinline__ float fast_tanh(float x) {
    x = fminf(fmaxf(x, -12.0f), 12.0f);
    const float e = __expf(2.0f * x);
    return __fdividef(e - 1.0f, e + 1.0f);
}

// ============================================================
// Kernel A v2: xp[s][b][j] = sum_d x[b][s][d]*Wx[d][j] + bias[j]
//   BK=32 (16 sync rounds instead of 32), W prefetch via cp.async
//   (no prefetch regs), X via 4-float4 register prefetch + smem
//   transpose. Dynamic smem 66.5KB, 2 CTAs/SM. Microkernel and
//   output mapping identical to the verified BK=16 version.
// ============================================================
#define GBK 32
#define XS_F (GBK * 128)          // one x buffer: [32][128]
#define WS_F (GBK * 132)          // one w buffer: [32][132] padded
#define GEMM_SMEM ((2 * XS_F + 2 * WS_F) * 4)   // 66560 B

__global__ void __launch_bounds__(256, 2) xp_gemm(
    const float* __restrict__ x,
    const float* __restrict__ Wx,
    const float* __restrict__ bias)
{
    extern __shared__ __align__(16) float gsm[];
    float* xs = gsm;                   // [2][GBK][128]
    float* ws = gsm + 2 * XS_F;        // [2][GBK][132]

    const int tid = threadIdx.x;
    const int tx = tid & 15, ty = tid >> 4;
    const int jn0 = blockIdx.x * 128;
    const int mt  = blockIdx.y;
    const int bb  = mt >> 3;
    const int s0  = (mt & 7) * 128;

    const float* xbase = x + ((size_t)bb * SEQ + s0) * DIN;
    const int la_tok = tid >> 2, la_kv = tid & 3;   // x loader: 64 toks x 4 kv
    const int wr = tid >> 3, wc = tid & 7;          // w loader: 32 rows x 8 col-groups

    uint32_t ws_u32;
    asm("{ .reg .u64 t; cvta.to.shared.u64 t, %1; cvt.u32.u64 %0, t; }"
        : "=r"(ws_u32) : "l"(ws));

    ull acc[4][8];
#pragma unroll
    for (int p = 0; p < 4; p++)
#pragma unroll
        for (int q = 0; q < 8; q++) acc[p][q] = 0ULL;

    // ---- prologue: fill buffer 0 ----
    {
        // W via cp.async: 4 x 16B per thread
#pragma unroll
        for (int q = 0; q < 4; q++) {
            const int col4 = wc + 8 * q;             // float4 slot 0..31
            const float* src = Wx + (size_t)wr * HID + jn0 + col4 * 4;
            const uint32_t dst = ws_u32 + (uint32_t)((wr * 132 + col4 * 4) * 4);
            asm volatile("cp.async.ca.shared.global [%0], [%1], 16;"
                         :: "r"(dst), "l"(src) : "memory");
        }
        asm volatile("cp.async.commit_group;" ::: "memory");
        // X via registers + transposed STS: 4 float4 per thread
#pragma unroll
        for (int h = 0; h < 2; h++) {
#pragma unroll
            for (int q = 0; q < 2; q++) {
                const int tok = la_tok + 64 * h;
                const int kb  = (la_kv + 4 * q) * 4;
                const float4 f = *(const float4*)(xbase + (size_t)tok * DIN + kb);
                xs[(kb + 0) * 128 + tok] = f.x;
                xs[(kb + 1) * 128 + tok] = f.y;
                xs[(kb + 2) * 128 + tok] = f.z;
                xs[(kb + 3) * 128 + tok] = f.w;
            }
        }
        asm volatile("cp.async.wait_group 0;" ::: "memory");
    }
    __syncthreads();

    int buf = 0;
    for (int kc = 0; kc < 16; kc++) {
        const bool pf = (kc + 1) < 16;
        const int nb = buf ^ 1;
        float4 xr4[4];
        if (pf) {
            const int k0 = (kc + 1) * GBK;
            // W prefetch via cp.async into nb
#pragma unroll
            for (int q = 0; q < 4; q++) {
                const int col4 = wc + 8 * q;
                const float* src = Wx + (size_t)(k0 + wr) * HID + jn0 + col4 * 4;
                const uint32_t dst = ws_u32 +
                    (uint32_t)((nb * WS_F + wr * 132 + col4 * 4) * 4);
                asm volatile("cp.async.ca.shared.global [%0], [%1], 16;"
                             :: "r"(dst), "l"(src) : "memory");
            }
            asm volatile("cp.async.commit_group;" ::: "memory");
            // X prefetch into registers
#pragma unroll
            for (int h = 0; h < 2; h++) {
#pragma unroll
                for (int q = 0; q < 2; q++) {
                    const int tok = la_tok + 64 * h;
                    const int kb  = (la_kv + 4 * q) * 4;
                    xr4[h * 2 + q] =
                        *(const float4*)(xbase + (size_t)tok * DIN + k0 + kb);
                }
            }
        }

        const float* xsb = xs + buf * XS_F;
        const float* wsb = ws + buf * WS_F;
#pragma unroll 8
        for (int kk = 0; kk < GBK; kk++) {
            const double2 xa = *(const double2*)&xsb[kk * 128 + ty * 8];
            const double2 xb = *(const double2*)&xsb[kk * 128 + ty * 8 + 4];
            const float4 w0 = *(const float4*)&wsb[kk * 132 + tx * 8];
            const float4 w1 = *(const float4*)&wsb[kk * 132 + tx * 8 + 4];
            ull xr[4];
            xr[0] = __double_as_longlong(xa.x);
            xr[1] = __double_as_longlong(xa.y);
            xr[2] = __double_as_longlong(xb.x);
            xr[3] = __double_as_longlong(xb.y);
            ull wd[8];
            wd[0]=dup2(w0.x); wd[1]=dup2(w0.y); wd[2]=dup2(w0.z); wd[3]=dup2(w0.w);
            wd[4]=dup2(w1.x); wd[5]=dup2(w1.y); wd[6]=dup2(w1.z); wd[7]=dup2(w1.w);
#pragma unroll
            for (int p = 0; p < 4; p++)
#pragma unroll
                for (int q = 0; q < 8; q++)
                    fma2(acc[p][q], xr[p], wd[q]);
        }

        if (pf) {
            float* xsn = xs + nb * XS_F;
#pragma unroll
            for (int h = 0; h < 2; h++) {
#pragma unroll
                for (int q = 0; q < 2; q++) {
                    const int tok = la_tok + 64 * h;
                    const int kb  = (la_kv + 4 * q) * 4;
                    const float4 f = xr4[h * 2 + q];
                    xsn[(kb + 0) * 128 + tok] = f.x;
                    xsn[(kb + 1) * 128 + tok] = f.y;
                    xsn[(kb + 2) * 128 + tok] = f.z;
                    xsn[(kb + 3) * 128 + tok] = f.w;
                }
            }
            asm volatile("cp.async.wait_group 0;" ::: "memory");
        }
        __syncthreads();
        buf ^= 1;
    }

    // epilogue: add bias, write xp[s][b][j]  (identical to verified version)
    const float4 bv0 = *(const float4*)&bias[jn0 + tx * 8];
    const float4 bv1 = *(const float4*)&bias[jn0 + tx * 8 + 4];
#pragma unroll
    for (int p = 0; p < 4; p++) {
        float lo[8], hi[8];
#pragma unroll
        for (int q = 0; q < 8; q++) unpack2(acc[p][q], lo[q], hi[q]);
        const int r0 = ty * 8 + 2 * p;
        float* o0 = g_xp + ((size_t)(s0 + r0) * BATCH + bb) * HID + jn0 + tx * 8;
        float* o1 = o0 + (size_t)BATCH * HID;
        float4 v;
        v.x=lo[0]+bv0.x; v.y=lo[1]+bv0.y; v.z=lo[2]+bv0.z; v.w=lo[3]+bv0.w; *(float4*)o0 = v;
        v.x=lo[4]+bv1.x; v.y=lo[5]+bv1.y; v.z=lo[6]+bv1.z; v.w=lo[7]+bv1.w; *(float4*)(o0+4) = v;
        v.x=hi[0]+bv0.x; v.y=hi[1]+bv0.y; v.z=hi[2]+bv0.z; v.w=hi[3]+bv0.w; *(float4*)o1 = v;
        v.x=hi[4]+bv1.x; v.y=hi[5]+bv1.y; v.z=hi[6]+bv1.z; v.w=hi[7]+bv1.w; *(float4*)(o1+4) = v;
    }
}

// ============================================================
// Kernel B: EXACT R8 scan (best: 5.90us/step) — per-source
// barriers, staging buffer, tid0 bulk issue. Unchanged.
// ============================================================
#define WHS_FLOATS (512 * 64)            // 128KB  Whs[k][64]
#define HB_FLOATS  (2 * 512 * 8)         //  32KB  hb[buf][k][8rows]
#define RED_ULL    (16 * 64 * 4)         //  32KB  red[ksl][col][4 pairs]
#define STG_ULL    (2 * 64 * 4)          //   4KB  stg[buf][col][rowpair]
#define SMEM_SCAN8 (WHS_FLOATS * 4 + HB_FLOATS * 4 + RED_ULL * 8 + STG_ULL * 8 + 160)
#define SLICE_TXB 2048u                   // one source slice

static __device__ __forceinline__ void bar_wait_cta(uint32_t mb, uint32_t parity) {
    uint32_t done;
    asm volatile(
        "{\n\t.reg .pred p;\n\t"
        "mbarrier.try_wait.parity.acquire.cta.shared::cta.b64 p, [%1], %2;\n\t"
        "selp.b32 %0, 1, 0, p;\n\t}"
        : "=r"(done) : "r"(mb), "r"(parity) : "memory");
    if (!done) {
        asm volatile(
            "{\n\t.reg .pred P1;\n\t"
            "W_%=:\n\t"
            "mbarrier.try_wait.parity.acquire.cta.shared::cta.b64 P1, [%0], %1, 0x989680;\n\t"
            "@P1 bra.uni D_%=;\n\t"
            "bra.uni W_%=;\n\t"
            "D_%=:\n\t}"
            :: "r"(mb), "r"(parity) : "memory");
    }
}

__global__ void __launch_bounds__(512, 1) __cluster_dims__(8, 1, 1)
rnn_scan(const float* __restrict__ Wh, float* __restrict__ out)
{
    extern __shared__ __align__(16) float smem[];
    float* Whs = smem;                        // [512][64]
    float* hb  = smem + WHS_FLOATS;           // [2][512][8]
    ull*   red = (ull*)(hb + HB_FLOATS);      // [16][64][4]
    ull*   stg = red + RED_ULL;               // [2][64][4]
    ull*   mbar = stg + STG_ULL;              // [2 buf][8 src]

    const int tid  = threadIdx.x;
    const int rank = blockIdx.x & 7;
    const int cid  = blockIdx.x >> 3;
    const int ksl  = tid >> 5;                // warp 0..15 : k-slice
    const int c2   = tid & 31;                // col-pair 0..31
    const int mysrc = ksl >> 1;               // source rank this warp consumes

    uint32_t mbar_u32, hb_u32, stg_u32;
    asm("{ .reg .u64 t; cvta.to.shared.u64 t, %1; cvt.u32.u64 %0, t; }"
        : "=r"(mbar_u32) : "l"(mbar));
    asm("{ .reg .u64 t; cvta.to.shared.u64 t, %1; cvt.u32.u64 %0, t; }"
        : "=r"(hb_u32) : "l"(hb));
    asm("{ .reg .u64 t; cvta.to.shared.u64 t, %1; cvt.u32.u64 %0, t; }"
        : "=r"(stg_u32) : "l"(stg));

    for (int i = tid; i < 512 * 16; i += 512) {
        const int k = i >> 4, jv = i & 15;
        *(float4*)&Whs[k * 64 + jv * 4] =
            *(const float4*)&Wh[(size_t)k * HID + rank * 64 + jv * 4];
    }
    for (int i = tid; i < HB_FLOATS; i += 512) hb[i] = 0.0f;
    if (tid < 16) {
        const uint32_t mb = mbar_u32 + (uint32_t)(tid * 8);
        asm volatile("mbarrier.init.shared.b64 [%0], 1;" :: "r"(mb) : "memory");
        asm volatile("mbarrier.arrive.expect_tx.shared.b64 _, [%0], %1;"
                     :: "r"(mb), "r"(SLICE_TXB) : "memory");
    }

    const int rp = tid >> 6;                  // row-pair 0..3
    const int c  = tid & 63;                  // col 0..63
    const int jg = rank * 64 + c;
    const int b0 = cid * 8 + 2 * rp;

    uint32_t pdst[8], pbar[8];
#pragma unroll
    for (int r = 0; r < 8; r++) {
        const uint32_t la = hb_u32 + (uint32_t)(rank * 2048);
        asm("mapa.shared::cluster.u32 %0, %1, %2;" : "=r"(pdst[r]) : "r"(la), "r"(r));
        const uint32_t lb = mbar_u32 + (uint32_t)(rank * 8);
        asm("mapa.shared::cluster.u32 %0, %1, %2;" : "=r"(pbar[r]) : "r"(lb), "r"(r));
    }

    asm volatile("barrier.cluster.arrive.aligned;" ::: "memory");
    asm volatile("barrier.cluster.wait.aligned;"   ::: "memory");

    const float* wp = Whs + (ksl * 32) * 64 + 2 * c2;
    const uint32_t mywait = mbar_u32 + (uint32_t)(mysrc * 8);

    for (int t = 0; t < SEQ; t++) {
        const int cur = t & 1, nb = cur ^ 1;

        float xp0 = 0.f, xp1 = 0.f;
        if (tid < 256) {
            const float* xpt = g_xp + (size_t)t * (BATCH * HID);
            xp0 = xpt[(size_t)b0 * HID + jg];
            xp1 = xpt[(size_t)(b0 + 1) * HID + jg];
        }

        if (t > 0) {
            const uint32_t parity = (uint32_t)(((t - 1) >> 1) & 1);
            const uint32_t mb = mywait + (uint32_t)(cur * 64);
            bar_wait_cta(mb, parity);
            if ((ksl & 1) == 0 && c2 == 0) {
                asm volatile("mbarrier.arrive.expect_tx.shared.b64 _, [%0], %1;"
                             :: "r"(mb), "r"(SLICE_TXB) : "memory");
            }
        }

        const ull* hc = (const ull*)(hb + cur * 4096) + (size_t)ksl * 32 * 4;
        ull a00=0, a01=0, a10=0, a11=0, a20=0, a21=0, a30=0, a31=0;
#pragma unroll 8
        for (int kk = 0; kk < 32; kk++) {
            const float2 w = *(const float2*)(wp + kk * 64);
            const ulonglong2 h01 = *(const ulonglong2*)(hc + kk * 4);
            const ulonglong2 h23 = *(const ulonglong2*)(hc + kk * 4 + 2);
            const ull w0 = dup2(w.x), w1 = dup2(w.y);
            fma2(a00, h01.x, w0); fma2(a01, h01.y, w0);
            fma2(a10, h23.x, w0); fma2(a11, h23.y, w0);
            fma2(a20, h01.x, w1); fma2(a21, h01.y, w1);
            fma2(a30, h23.x, w1); fma2(a31, h23.y, w1);
        }
        {
            ulonglong2 v;
            v.x = a00; v.y = a01;
            *(ulonglong2*)&red[((size_t)ksl * 64 + 2*c2) * 4]     = v;
            v.x = a10; v.y = a11;
            *(ulonglong2*)&red[((size_t)ksl * 64 + 2*c2) * 4 + 2] = v;
            v.x = a20; v.y = a21;
            *(ulonglong2*)&red[((size_t)ksl * 64 + 2*c2 + 1) * 4]     = v;
            v.x = a30; v.y = a31;
            *(ulonglong2*)&red[((size_t)ksl * 64 + 2*c2 + 1) * 4 + 2] = v;
        }
        __syncthreads();   // sync1: all partials visible

        if (tid < 256) {
            const ull* rbase = red + (size_t)c * 4 + rp;
            ull s[8];
#pragma unroll
            for (int i = 0; i < 8; i++)
                s[i] = add2v(rbase[(size_t)(2 * i) * 256], rbase[(size_t)(2 * i + 1) * 256]);
            s[0] = add2v(s[0], s[1]); s[2] = add2v(s[2], s[3]);
            s[4] = add2v(s[4], s[5]); s[6] = add2v(s[6], s[7]);
            s[0] = add2v(s[0], s[2]); s[4] = add2v(s[4], s[6]);
            s[0] = add2v(s[0], s[4]);
            float lo, hi; unpack2(s[0], lo, hi);
            const float v0 = fast_tanh(lo + xp0);
            const float v1 = fast_tanh(hi + xp1);
            stg[(size_t)nb * 256 + c * 4 + rp] = pack2(v0, v1);
        }
        __syncthreads();   // sync2: staging complete; red free for t+1

        if (tid == 0) {
            asm volatile("fence.proxy.async.shared::cta;" ::: "memory");
            const uint32_t src  = stg_u32 + (uint32_t)(nb * 2048);
            const uint32_t doff = (uint32_t)(nb * 16384);
            const uint32_t boff = (uint32_t)(nb * 64);
#pragma unroll
            for (int r = 0; r < 8; r++) {
                asm volatile(
                    "cp.async.bulk.shared::cluster.shared::cta.mbarrier::complete_tx::bytes "
                    "[%0], [%1], %2, [%3];"
                    :: "r"(pdst[r] + doff), "r"(src), "r"(SLICE_TXB), "r"(pbar[r] + boff)
                    : "memory");
            }
        }
    }

    bar_wait_cta(mywait, 1u);
    __syncthreads();
    if (tid < 256) {
        const float2 hv = *(const float2*)&hb[jg * 8 + 2 * rp];
        out[(size_t)b0 * HID + jg]       = hv.x;
        out[(size_t)(b0 + 1) * HID + jg] = hv.y;
    }

    asm volatile("barrier.cluster.arrive.aligned;" ::: "memory");
    asm volatile("barrier.cluster.wait.aligned;"   ::: "memory");
}

// ============================================================
extern "C" void kernel_launch(void* const* d_in, const int* in_sizes, int n_in,
                              void* d_out, int out_size)
{
    (void)in_sizes; (void)n_in; (void)out_size;
    const float* x    = (const float*)d_in[0];
    const float* Wx   = (const float*)d_in[1];
    const float* Wh   = (const float*)d_in[2];
    const float* bias = (const float*)d_in[3];
    float* out = (float*)d_out;

    cudaFuncSetAttribute(xp_gemm, cudaFuncAttributeMaxDynamicSharedMemorySize, GEMM_SMEM);
    cudaFuncSetAttribute(rnn_scan, cudaFuncAttributeMaxDynamicSharedMemorySize, SMEM_SCAN8);

    dim3 g1(4, 1024);
    xp_gemm<<<g1, 256, GEMM_SMEM>>>(x, Wx, bias);
    rnn_scan<<<128, 512, SMEM_SCAN8>>>(Wh, out);
}

// round 14
// speedup vs baseline: 1.0460x; 1.0460x over previous
#include <cuda_runtime.h>
#include <cstdint>
#include <cstddef>

#define BATCH 128
#define SEQ   1024
#define DIN   512
#define HID   512

// xp[s][b][h] scratch: 1024*128*512 fp32 = 256MB (device global — allocation-free)
__device__ float g_xp[SEQ * BATCH * HID];
// h-exchange bounce buffer: [cid][buf][rank][512 floats] = 512KB
__device__ __align__(16) float g_hx[16][2][8][512];

typedef unsigned long long ull;
static __device__ __forceinline__ ull dup2(float a) {
    ull r; asm("mov.b64 %0, {%1, %1};" : "=l"(r) : "f"(a)); return r;
}
static __device__ __forceinline__ ull pack2(float a, float b) {
    ull r; asm("mov.b64 %0, {%1, %2};" : "=l"(r) : "f"(a), "f"(b)); return r;
}
static __device__ __forceinline__ void unpack2(ull v, float& lo, float& hi) {
    asm("mov.b64 {%0, %1}, %2;" : "=f"(lo), "=f"(hi) : "l"(v));
}
static __device__ __forceinline__ void fma2(ull& acc, ull a, ull b) {
    asm("fma.rn.f32x2 %0, %1, %2, %0;" : "+l"(acc) : "l"(a), "l"(b));
}
static __device__ __forceinline__ ull add2v(ull a, ull b) {
    ull r; asm("add.rn.f32x2 %0, %1, %2;" : "=l"(r) : "l"(a), "l"(b)); return r;
}
static __device__ __forceinline__ float fast_tanh(float x) {
    x = fminf(fmaxf(x, -12.0f), 12.0f);
    const float e = __expf(2.0f * x);
    return __fdividef(e - 1.0f, e + 1.0f);
}

// ============================================================
// Kernel A: xp GEMM — reverted to the verified BK=16 version
// (static smem, register double-buffer; ~1.36ms)
// ============================================================
__global__ void __launch_bounds__(256, 2) xp_gemm(
    const float* __restrict__ x,
    const float* __restrict__ Wx,
    const float* __restrict__ bias)
{
    __shared__ __align__(16) float xs[2][16][128];
    __shared__ __align__(16) float ws[2][16][132];

    const int tid = threadIdx.x;
    const int tx = tid & 15, ty = tid >> 4;
    const int jn0 = blockIdx.x * 128;
    const int mt  = blockIdx.y;
    const int bb  = mt >> 3;
    const int s0  = (mt & 7) * 128;

    const float* xbase = x + ((size_t)bb * SEQ + s0) * DIN;
    const int la_tok = tid >> 2, la_kv = tid & 3;
    const int lb_row = tid >> 5, lb_jv = tid & 31;

    ull acc[4][8];
#pragma unroll
    for (int p = 0; p < 4; p++)
#pragma unroll
        for (int q = 0; q < 8; q++) acc[p][q] = 0ULL;

    {
        float4 ra0 = *(const float4*)(xbase + (size_t)la_tok * DIN + la_kv * 4);
        float4 ra1 = *(const float4*)(xbase + (size_t)(la_tok + 64) * DIN + la_kv * 4);
        float4 rb0 = *(const float4*)(Wx + (size_t)lb_row * HID + jn0 + lb_jv * 4);
        float4 rb1 = *(const float4*)(Wx + (size_t)(lb_row + 8) * HID + jn0 + lb_jv * 4);
        xs[0][la_kv*4+0][la_tok]=ra0.x; xs[0][la_kv*4+1][la_tok]=ra0.y;
        xs[0][la_kv*4+2][la_tok]=ra0.z; xs[0][la_kv*4+3][la_tok]=ra0.w;
        xs[0][la_kv*4+0][la_tok+64]=ra1.x; xs[0][la_kv*4+1][la_tok+64]=ra1.y;
        xs[0][la_kv*4+2][la_tok+64]=ra1.z; xs[0][la_kv*4+3][la_tok+64]=ra1.w;
        *(float4*)&ws[0][lb_row][lb_jv*4]   = rb0;
        *(float4*)&ws[0][lb_row+8][lb_jv*4] = rb1;
    }
    __syncthreads();

    int buf = 0;
    for (int kc = 0; kc < 32; kc++) {
        float4 ra0, ra1, rb0, rb1;
        const bool pf = (kc + 1) < 32;
        if (pf) {
            const int k0 = (kc + 1) * 16;
            ra0 = *(const float4*)(xbase + (size_t)la_tok * DIN + k0 + la_kv * 4);
            ra1 = *(const float4*)(xbase + (size_t)(la_tok + 64) * DIN + k0 + la_kv * 4);
            rb0 = *(const float4*)(Wx + (size_t)(k0 + lb_row) * HID + jn0 + lb_jv * 4);
            rb1 = *(const float4*)(Wx + (size_t)(k0 + lb_row + 8) * HID + jn0 + lb_jv * 4);
        }
#pragma unroll
        for (int kk = 0; kk < 16; kk++) {
            const double2 xa = *(const double2*)&xs[buf][kk][ty * 8];
            const double2 xb = *(const double2*)&xs[buf][kk][ty * 8 + 4];
            const float4 w0 = *(const float4*)&ws[buf][kk][tx * 8];
            const float4 w1 = *(const float4*)&ws[buf][kk][tx * 8 + 4];
            ull xr[4];
            xr[0] = __double_as_longlong(xa.x);
            xr[1] = __double_as_longlong(xa.y);
            xr[2] = __double_as_longlong(xb.x);
            xr[3] = __double_as_longlong(xb.y);
            ull wd[8];
            wd[0]=dup2(w0.x); wd[1]=dup2(w0.y); wd[2]=dup2(w0.z); wd[3]=dup2(w0.w);
            wd[4]=dup2(w1.x); wd[5]=dup2(w1.y); wd[6]=dup2(w1.z); wd[7]=dup2(w1.w);
#pragma unroll
            for (int p = 0; p < 4; p++)
#pragma unroll
                for (int q = 0; q < 8; q++)
                    fma2(acc[p][q], xr[p], wd[q]);
        }
        if (pf) {
            const int nb = buf ^ 1;
            xs[nb][la_kv*4+0][la_tok]=ra0.x; xs[nb][la_kv*4+1][la_tok]=ra0.y;
            xs[nb][la_kv*4+2][la_tok]=ra0.z; xs[nb][la_kv*4+3][la_tok]=ra0.w;
            xs[nb][la_kv*4+0][la_tok+64]=ra1.x; xs[nb][la_kv*4+1][la_tok+64]=ra1.y;
            xs[nb][la_kv*4+2][la_tok+64]=ra1.z; xs[nb][la_kv*4+3][la_tok+64]=ra1.w;
            *(float4*)&ws[nb][lb_row][lb_jv*4]   = rb0;
            *(float4*)&ws[nb][lb_row+8][lb_jv*4] = rb1;
        }
        __syncthreads();
        buf ^= 1;
    }

    const float4 bv0 = *(const float4*)&bias[jn0 + tx * 8];
    const float4 bv1 = *(const float4*)&bias[jn0 + tx * 8 + 4];
#pragma unroll
    for (int p = 0; p < 4; p++) {
        float lo[8], hi[8];
#pragma unroll
        for (int q = 0; q < 8; q++) unpack2(acc[p][q], lo[q], hi[q]);
        const int r0 = ty * 8 + 2 * p;
        float* o0 = g_xp + ((size_t)(s0 + r0) * BATCH + bb) * HID + jn0 + tx * 8;
        float* o1 = o0 + (size_t)BATCH * HID;
        float4 v;
        v.x=lo[0]+bv0.x; v.y=lo[1]+bv0.y; v.z=lo[2]+bv0.z; v.w=lo[3]+bv0.w; *(float4*)o0 = v;
        v.x=lo[4]+bv1.x; v.y=lo[5]+bv1.y; v.z=lo[6]+bv1.z; v.w=lo[7]+bv1.w; *(float4*)(o0+4) = v;
        v.x=hi[0]+bv0.x; v.y=hi[1]+bv0.y; v.z=hi[2]+bv0.z; v.w=hi[3]+bv0.w; *(float4*)o1 = v;
        v.x=hi[4]+bv1.x; v.y=hi[5]+bv1.y; v.z=hi[6]+bv1.z; v.w=hi[7]+bv1.w; *(float4*)(o1+4) = v;
    }
}

// ============================================================
// Kernel B v14: R8 protocol, transport = gmem bounce + ONE
//   multicast bulk copy per CTA per step (instead of 8 pushes).
//   tid0: bulk store slice -> gmem slot; wait; multicast bulk
//   load gmem -> all 8 CTAs' hb with complete_tx on each dest's
//   per-source barrier. Everything else identical to R8.
// ============================================================
#define WHS_FLOATS (512 * 64)            // 128KB  Whs[k][64]
#define HB_FLOATS  (2 * 512 * 8)         //  32KB  hb[buf][k][8rows]
#define RED_ULL    (16 * 64 * 4)         //  32KB  red[ksl][col][4 pairs]
#define STG_ULL    (2 * 64 * 4)          //   4KB  stg[buf][col][rowpair]
#define SMEM_SCAN8 (WHS_FLOATS * 4 + HB_FLOATS * 4 + RED_ULL * 8 + STG_ULL * 8 + 160)
#define SLICE_TXB 2048u                   // one source slice

static __device__ __forceinline__ void bar_wait_cta(uint32_t mb, uint32_t parity) {
    uint32_t done;
    asm volatile(
        "{\n\t.reg .pred p;\n\t"
        "mbarrier.try_wait.parity.acquire.cta.shared::cta.b64 p, [%1], %2;\n\t"
        "selp.b32 %0, 1, 0, p;\n\t}"
        : "=r"(done) : "r"(mb), "r"(parity) : "memory");
    if (!done) {
        asm volatile(
            "{\n\t.reg .pred P1;\n\t"
            "W_%=:\n\t"
            "mbarrier.try_wait.parity.acquire.cta.shared::cta.b64 P1, [%0], %1, 0x989680;\n\t"
            "@P1 bra.uni D_%=;\n\t"
            "bra.uni W_%=;\n\t"
            "D_%=:\n\t}"
            :: "r"(mb), "r"(parity) : "memory");
    }
}

__global__ void __launch_bounds__(512, 1) __cluster_dims__(8, 1, 1)
rnn_scan(const float* __restrict__ Wh, float* __restrict__ out)
{
    extern __shared__ __align__(16) float smem[];
    float* Whs = smem;                        // [512][64]
    float* hb  = smem + WHS_FLOATS;           // [2][512][8]
    ull*   red = (ull*)(hb + HB_FLOATS);      // [16][64][4]
    ull*   stg = red + RED_ULL;               // [2][64][4]
    ull*   mbar = stg + STG_ULL;              // [2 buf][8 src]

    const int tid  = threadIdx.x;
    const int rank = blockIdx.x & 7;
    const int cid  = blockIdx.x >> 3;
    const int ksl  = tid >> 5;                // warp 0..15 : k-slice
    const int c2   = tid & 31;                // col-pair 0..31
    const int mysrc = ksl >> 1;               // source rank this warp consumes

    uint32_t mbar_u32, hb_u32, stg_u32;
    asm("{ .reg .u64 t; cvta.to.shared.u64 t, %1; cvt.u32.u64 %0, t; }"
        : "=r"(mbar_u32) : "l"(mbar));
    asm("{ .reg .u64 t; cvta.to.shared.u64 t, %1; cvt.u32.u64 %0, t; }"
        : "=r"(hb_u32) : "l"(hb));
    asm("{ .reg .u64 t; cvta.to.shared.u64 t, %1; cvt.u32.u64 %0, t; }"
        : "=r"(stg_u32) : "l"(stg));

    for (int i = tid; i < 512 * 16; i += 512) {
        const int k = i >> 4, jv = i & 15;
        *(float4*)&Whs[k * 64 + jv * 4] =
            *(const float4*)&Wh[(size_t)k * HID + rank * 64 + jv * 4];
    }
    for (int i = tid; i < HB_FLOATS; i += 512) hb[i] = 0.0f;
    if (tid < 16) {
        const uint32_t mb = mbar_u32 + (uint32_t)(tid * 8);
        asm volatile("mbarrier.init.shared.b64 [%0], 1;" :: "r"(mb) : "memory");
        asm volatile("mbarrier.arrive.expect_tx.shared.b64 _, [%0], %1;"
                     :: "r"(mb), "r"(SLICE_TXB) : "memory");
    }

    const int rp = tid >> 6;                  // row-pair 0..3
    const int c  = tid & 63;                  // col 0..63
    const int jg = rank * 64 + c;
    const int b0 = cid * 8 + 2 * rp;

    asm volatile("barrier.cluster.arrive.aligned;" ::: "memory");
    asm volatile("barrier.cluster.wait.aligned;"   ::: "memory");

    const float* wp = Whs + (ksl * 32) * 64 + 2 * c2;
    const uint32_t mywait = mbar_u32 + (uint32_t)(mysrc * 8);

    for (int t = 0; t < SEQ; t++) {
        const int cur = t & 1, nb = cur ^ 1;

        float xp0 = 0.f, xp1 = 0.f;
        if (tid < 256) {
            const float* xpt = g_xp + (size_t)t * (BATCH * HID);
            xp0 = xpt[(size_t)b0 * HID + jg];
            xp1 = xpt[(size_t)(b0 + 1) * HID + jg];
        }

        if (t > 0) {
            const uint32_t parity = (uint32_t)(((t - 1) >> 1) & 1);
            const uint32_t mb = mywait + (uint32_t)(cur * 64);
            bar_wait_cta(mb, parity);
            if ((ksl & 1) == 0 && c2 == 0) {
                asm volatile("mbarrier.arrive.expect_tx.shared.b64 _, [%0], %1;"
                             :: "r"(mb), "r"(SLICE_TXB) : "memory");
            }
        }

        const ull* hc = (const ull*)(hb + cur * 4096) + (size_t)ksl * 32 * 4;
        ull a00=0, a01=0, a10=0, a11=0, a20=0, a21=0, a30=0, a31=0;
#pragma unroll 8
        for (int kk = 0; kk < 32; kk++) {
            const float2 w = *(const float2*)(wp + kk * 64);
            const ulonglong2 h01 = *(const ulonglong2*)(hc + kk * 4);
            const ulonglong2 h23 = *(const ulonglong2*)(hc + kk * 4 + 2);
            const ull w0 = dup2(w.x), w1 = dup2(w.y);
            fma2(a00, h01.x, w0); fma2(a01, h01.y, w0);
            fma2(a10, h23.x, w0); fma2(a11, h23.y, w0);
            fma2(a20, h01.x, w1); fma2(a21, h01.y, w1);
            fma2(a30, h23.x, w1); fma2(a31, h23.y, w1);
        }
        {
            ulonglong2 v;
            v.x = a00; v.y = a01;
            *(ulonglong2*)&red[((size_t)ksl * 64 + 2*c2) * 4]     = v;
            v.x = a10; v.y = a11;
            *(ulonglong2*)&red[((size_t)ksl * 64 + 2*c2) * 4 + 2] = v;
            v.x = a20; v.y = a21;
            *(ulonglong2*)&red[((size_t)ksl * 64 + 2*c2 + 1) * 4]     = v;
            v.x = a30; v.y = a31;
            *(ulonglong2*)&red[((size_t)ksl * 64 + 2*c2 + 1) * 4 + 2] = v;
        }
        __syncthreads();   // sync1: all partials visible

        if (tid < 256) {
            const ull* rbase = red + (size_t)c * 4 + rp;
            ull s[8];
#pragma unroll
            for (int i = 0; i < 8; i++)
                s[i] = add2v(rbase[(size_t)(2 * i) * 256], rbase[(size_t)(2 * i + 1) * 256]);
            s[0] = add2v(s[0], s[1]); s[2] = add2v(s[2], s[3]);
            s[4] = add2v(s[4], s[5]); s[6] = add2v(s[6], s[7]);
            s[0] = add2v(s[0], s[2]); s[4] = add2v(s[4], s[6]);
            s[0] = add2v(s[0], s[4]);
            float lo, hi; unpack2(s[0], lo, hi);
            const float v0 = fast_tanh(lo + xp0);
            const float v1 = fast_tanh(hi + xp1);
            stg[(size_t)nb * 256 + c * 4 + rp] = pack2(v0, v1);
        }
        __syncthreads();   // sync2: staging complete; red free for t+1

        if (tid == 0) {
            asm volatile("fence.proxy.async.shared::cta;" ::: "memory");
            float* gslot = &g_hx[cid][nb][rank][0];
            const uint32_t src = stg_u32 + (uint32_t)(nb * 2048);
            // 1) ship slice to gmem (L2)
            asm volatile(
                "cp.async.bulk.global.shared::cta.bulk_group [%0], [%1], %2;"
                :: "l"(gslot), "r"(src), "r"(SLICE_TXB) : "memory");
            asm volatile("cp.async.bulk.commit_group;" ::: "memory");
            asm volatile("cp.async.bulk.wait_group 0;" ::: "memory");
            // 2) ONE multicast bulk load: gmem -> hb[nb] slice of ALL 8 CTAs,
            //    complete_tx(2048) on each dest's mbar[nb][rank]
            const uint32_t dst = hb_u32 + (uint32_t)(nb * 16384 + rank * 2048);
            const uint32_t mb  = mbar_u32 + (uint32_t)((nb * 8 + rank) * 8);
            const unsigned short mask = 0xFF;
            asm volatile(
                "cp.async.bulk.shared::cluster.global.mbarrier::complete_tx::bytes.multicast::cluster "
                "[%0], [%1], %2, [%3], %4;"
                :: "r"(dst), "l"(gslot), "r"(SLICE_TXB), "r"(mb), "h"(mask)
                : "memory");
        }
    }

    bar_wait_cta(mywait, 1u);
    __syncthreads();
    if (tid < 256) {
        const float2 hv = *(const float2*)&hb[jg * 8 + 2 * rp];
        out[(size_t)b0 * HID + jg]       = hv.x;
        out[(size_t)(b0 + 1) * HID + jg] = hv.y;
    }

    asm volatile("barrier.cluster.arrive.aligned;" ::: "memory");
    asm volatile("barrier.cluster.wait.aligned;"   ::: "memory");
}

// ============================================================
extern "C" void kernel_launch(void* const* d_in, const int* in_sizes, int n_in,
                              void* d_out, int out_size)
{
    (void)in_sizes; (void)n_in; (void)out_size;
    const float* x    = (const float*)d_in[0];
    const float* Wx   = (const float*)d_in[1];
    const float* Wh   = (const float*)d_in[2];
    const float* bias = (const float*)d_in[3];
    float* out = (float*)d_out;

    cudaFuncSetAttribute(rnn_scan, cudaFuncAttributeMaxDynamicSharedMemorySize, SMEM_SCAN8);

    dim3 g1(4, 1024);
    xp_gemm<<<g1, 256>>>(x, Wx, bias);
    rnn_scan<<<128, 512, SMEM_SCAN8>>>(Wh, out);
}

// round 15
// speedup vs baseline: 1.2977x; 1.2406x over previous
#include <cuda_runtime.h>
#include <cstdint>
#include <cstddef>

#define BATCH 128
#define SEQ   1024
#define DIN   512
#define HID   512

// xp[s][b][h] scratch: 1024*128*512 fp32 = 256MB (device global — allocation-free)
__device__ float g_xp[SEQ * BATCH * HID];

typedef unsigned long long ull;
static __device__ __forceinline__ ull dup2(float a) {
    ull r; asm("mov.b64 %0, {%1, %1};" : "=l"(r) : "f"(a)); return r;
}
static __device__ __forceinline__ ull pack2(float a, float b) {
    ull r; asm("mov.b64 %0, {%1, %2};" : "=l"(r) : "f"(a), "f"(b)); return r;
}
static __device__ __forceinline__ void unpack2(ull v, float& lo, float& hi) {
    asm("mov.b64 {%0, %1}, %2;" : "=f"(lo), "=f"(hi) : "l"(v));
}
static __device__ __forceinline__ void fma2(ull& acc, ull a, ull b) {
    asm("fma.rn.f32x2 %0, %1, %2, %0;" : "+l"(acc) : "l"(a), "l"(b));
}
static __device__ __forceinline__ ull add2v(ull a, ull b) {
    ull r; asm("add.rn.f32x2 %0, %1, %2;" : "=l"(r) : "l"(a), "l"(b)); return r;
}
static __device__ __forceinline__ float fast_tanh(float x) {
    x = fminf(fmaxf(x, -12.0f), 12.0f);
    const float e = __expf(2.0f * x);
    return __fdividef(e - 1.0f, e + 1.0f);
}

// ============================================================
// Kernel A: xp GEMM — verified BK=16 version (~1.36ms)
// ============================================================
__global__ void __launch_bounds__(256, 2) xp_gemm(
    const float* __restrict__ x,
    const float* __restrict__ Wx,
    const float* __restrict__ bias)
{
    __shared__ __align__(16) float xs[2][16][128];
    __shared__ __align__(16) float ws[2][16][132];

    const int tid = threadIdx.x;
    const int tx = tid & 15, ty = tid >> 4;
    const int jn0 = blockIdx.x * 128;
    const int mt  = blockIdx.y;
    const int bb  = mt >> 3;
    const int s0  = (mt & 7) * 128;

    const float* xbase = x + ((size_t)bb * SEQ + s0) * DIN;
    const int la_tok = tid >> 2, la_kv = tid & 3;
    const int lb_row = tid >> 5, lb_jv = tid & 31;

    ull acc[4][8];
#pragma unroll
    for (int p = 0; p < 4; p++)
#pragma unroll
        for (int q = 0; q < 8; q++) acc[p][q] = 0ULL;

    {
        float4 ra0 = *(const float4*)(xbase + (size_t)la_tok * DIN + la_kv * 4);
        float4 ra1 = *(const float4*)(xbase + (size_t)(la_tok + 64) * DIN + la_kv * 4);
        float4 rb0 = *(const float4*)(Wx + (size_t)lb_row * HID + jn0 + lb_jv * 4);
        float4 rb1 = *(const float4*)(Wx + (size_t)(lb_row + 8) * HID + jn0 + lb_jv * 4);
        xs[0][la_kv*4+0][la_tok]=ra0.x; xs[0][la_kv*4+1][la_tok]=ra0.y;
        xs[0][la_kv*4+2][la_tok]=ra0.z; xs[0][la_kv*4+3][la_tok]=ra0.w;
        xs[0][la_kv*4+0][la_tok+64]=ra1.x; xs[0][la_kv*4+1][la_tok+64]=ra1.y;
        xs[0][la_kv*4+2][la_tok+64]=ra1.z; xs[0][la_kv*4+3][la_tok+64]=ra1.w;
        *(float4*)&ws[0][lb_row][lb_jv*4]   = rb0;
        *(float4*)&ws[0][lb_row+8][lb_jv*4] = rb1;
    }
    __syncthreads();

    int buf = 0;
    for (int kc = 0; kc < 32; kc++) {
        float4 ra0, ra1, rb0, rb1;
        const bool pf = (kc + 1) < 32;
        if (pf) {
            const int k0 = (kc + 1) * 16;
            ra0 = *(const float4*)(xbase + (size_t)la_tok * DIN + k0 + la_kv * 4);
            ra1 = *(const float4*)(xbase + (size_t)(la_tok + 64) * DIN + k0 + la_kv * 4);
            rb0 = *(const float4*)(Wx + (size_t)(k0 + lb_row) * HID + jn0 + lb_jv * 4);
            rb1 = *(const float4*)(Wx + (size_t)(k0 + lb_row + 8) * HID + jn0 + lb_jv * 4);
        }
#pragma unroll
        for (int kk = 0; kk < 16; kk++) {
            const double2 xa = *(const double2*)&xs[buf][kk][ty * 8];
            const double2 xb = *(const double2*)&xs[buf][kk][ty * 8 + 4];
            const float4 w0 = *(const float4*)&ws[buf][kk][tx * 8];
            const float4 w1 = *(const float4*)&ws[buf][kk][tx * 8 + 4];
            ull xr[4];
            xr[0] = __double_as_longlong(xa.x);
            xr[1] = __double_as_longlong(xa.y);
            xr[2] = __double_as_longlong(xb.x);
            xr[3] = __double_as_longlong(xb.y);
            ull wd[8];
            wd[0]=dup2(w0.x); wd[1]=dup2(w0.y); wd[2]=dup2(w0.z); wd[3]=dup2(w0.w);
            wd[4]=dup2(w1.x); wd[5]=dup2(w1.y); wd[6]=dup2(w1.z); wd[7]=dup2(w1.w);
#pragma unroll
            for (int p = 0; p < 4; p++)
#pragma unroll
                for (int q = 0; q < 8; q++)
                    fma2(acc[p][q], xr[p], wd[q]);
        }
        if (pf) {
            const int nb = buf ^ 1;
            xs[nb][la_kv*4+0][la_tok]=ra0.x; xs[nb][la_kv*4+1][la_tok]=ra0.y;
            xs[nb][la_kv*4+2][la_tok]=ra0.z; xs[nb][la_kv*4+3][la_tok]=ra0.w;
            xs[nb][la_kv*4+0][la_tok+64]=ra1.x; xs[nb][la_kv*4+1][la_tok+64]=ra1.y;
            xs[nb][la_kv*4+2][la_tok+64]=ra1.z; xs[nb][la_kv*4+3][la_tok+64]=ra1.w;
            *(float4*)&ws[nb][lb_row][lb_jv*4]   = rb0;
            *(float4*)&ws[nb][lb_row+8][lb_jv*4] = rb1;
        }
        __syncthreads();
        buf ^= 1;
    }

    const float4 bv0 = *(const float4*)&bias[jn0 + tx * 8];
    const float4 bv1 = *(const float4*)&bias[jn0 + tx * 8 + 4];
#pragma unroll
    for (int p = 0; p < 4; p++) {
        float lo[8], hi[8];
#pragma unroll
        for (int q = 0; q < 8; q++) unpack2(acc[p][q], lo[q], hi[q]);
        const int r0 = ty * 8 + 2 * p;
        float* o0 = g_xp + ((size_t)(s0 + r0) * BATCH + bb) * HID + jn0 + tx * 8;
        float* o1 = o0 + (size_t)BATCH * HID;
        float4 v;
        v.x=lo[0]+bv0.x; v.y=lo[1]+bv0.y; v.z=lo[2]+bv0.z; v.w=lo[3]+bv0.w; *(float4*)o0 = v;
        v.x=lo[4]+bv1.x; v.y=lo[5]+bv1.y; v.z=lo[6]+bv1.z; v.w=lo[7]+bv1.w; *(float4*)(o0+4) = v;
        v.x=hi[0]+bv0.x; v.y=hi[1]+bv0.y; v.z=hi[2]+bv0.z; v.w=hi[3]+bv0.w; *(float4*)o1 = v;
        v.x=hi[4]+bv1.x; v.y=hi[5]+bv1.y; v.z=hi[6]+bv1.z; v.w=hi[7]+bv1.w; *(float4*)(o1+4) = v;
    }
}

// ============================================================
// Kernel B v15: EXACT R8 protocol/transport; ONLY change is the
//   red layout red[pair][ksl][col] so reduce loads are lane-
//   contiguous (conflict-free) instead of 8-way bank-conflicted.
// ============================================================
#define WHS_FLOATS (512 * 64)            // 128KB  Whs[k][64]
#define HB_FLOATS  (2 * 512 * 8)         //  32KB  hb[buf][k][8rows]
#define RED_ULL    (4 * 16 * 64)         //  32KB  red[pair][ksl][col]
#define STG_ULL    (2 * 64 * 4)          //   4KB  stg[buf][col][rowpair]
#define SMEM_SCAN8 (WHS_FLOATS * 4 + HB_FLOATS * 4 + RED_ULL * 8 + STG_ULL * 8 + 160)
#define SLICE_TXB 2048u                   // one source slice

static __device__ __forceinline__ void bar_wait_cta(uint32_t mb, uint32_t parity) {
    uint32_t done;
    asm volatile(
        "{\n\t.reg .pred p;\n\t"
        "mbarrier.try_wait.parity.acquire.cta.shared::cta.b64 p, [%1], %2;\n\t"
        "selp.b32 %0, 1, 0, p;\n\t}"
        : "=r"(done) : "r"(mb), "r"(parity) : "memory");
    if (!done) {
        asm volatile(
            "{\n\t.reg .pred P1;\n\t"
            "W_%=:\n\t"
            "mbarrier.try_wait.parity.acquire.cta.shared::cta.b64 P1, [%0], %1, 0x989680;\n\t"
            "@P1 bra.uni D_%=;\n\t"
            "bra.uni W_%=;\n\t"
            "D_%=:\n\t}"
            :: "r"(mb), "r"(parity) : "memory");
    }
}

__global__ void __launch_bounds__(512, 1) __cluster_dims__(8, 1, 1)
rnn_scan(const float* __restrict__ Wh, float* __restrict__ out)
{
    extern __shared__ __align__(16) float smem[];
    float* Whs = smem;                        // [512][64]
    float* hb  = smem + WHS_FLOATS;           // [2][512][8]
    ull*   red = (ull*)(hb + HB_FLOATS);      // [4 pair][16 ksl][64 col]
    ull*   stg = red + RED_ULL;               // [2][64][4]
    ull*   mbar = stg + STG_ULL;              // [2 buf][8 src]

    const int tid  = threadIdx.x;
    const int rank = blockIdx.x & 7;
    const int cid  = blockIdx.x >> 3;
    const int ksl  = tid >> 5;                // warp 0..15 : k-slice
    const int c2   = tid & 31;                // col-pair 0..31
    const int mysrc = ksl >> 1;               // source rank this warp consumes

    uint32_t mbar_u32, hb_u32, stg_u32;
    asm("{ .reg .u64 t; cvta.to.shared.u64 t, %1; cvt.u32.u64 %0, t; }"
        : "=r"(mbar_u32) : "l"(mbar));
    asm("{ .reg .u64 t; cvta.to.shared.u64 t, %1; cvt.u32.u64 %0, t; }"
        : "=r"(hb_u32) : "l"(hb));
    asm("{ .reg .u64 t; cvta.to.shared.u64 t, %1; cvt.u32.u64 %0, t; }"
        : "=r"(stg_u32) : "l"(stg));

    for (int i = tid; i < 512 * 16; i += 512) {
        const int k = i >> 4, jv = i & 15;
        *(float4*)&Whs[k * 64 + jv * 4] =
            *(const float4*)&Wh[(size_t)k * HID + rank * 64 + jv * 4];
    }
    for (int i = tid; i < HB_FLOATS; i += 512) hb[i] = 0.0f;
    if (tid < 16) {
        const uint32_t mb = mbar_u32 + (uint32_t)(tid * 8);
        asm volatile("mbarrier.init.shared.b64 [%0], 1;" :: "r"(mb) : "memory");
        asm volatile("mbarrier.arrive.expect_tx.shared.b64 _, [%0], %1;"
                     :: "r"(mb), "r"(SLICE_TXB) : "memory");
    }

    const int rp = tid >> 6;                  // row-pair 0..3
    const int c  = tid & 63;                  // col 0..63
    const int jg = rank * 64 + c;
    const int b0 = cid * 8 + 2 * rp;

    uint32_t pdst[8], pbar[8];
#pragma unroll
    for (int r = 0; r < 8; r++) {
        const uint32_t la = hb_u32 + (uint32_t)(rank * 2048);
        asm("mapa.shared::cluster.u32 %0, %1, %2;" : "=r"(pdst[r]) : "r"(la), "r"(r));
        const uint32_t lb = mbar_u32 + (uint32_t)(rank * 8);
        asm("mapa.shared::cluster.u32 %0, %1, %2;" : "=r"(pbar[r]) : "r"(lb), "r"(r));
    }

    asm volatile("barrier.cluster.arrive.aligned;" ::: "memory");
    asm volatile("barrier.cluster.wait.aligned;"   ::: "memory");

    const float* wp = Whs + (ksl * 32) * 64 + 2 * c2;
    const uint32_t mywait = mbar_u32 + (uint32_t)(mysrc * 8);

    for (int t = 0; t < SEQ; t++) {
        const int cur = t & 1, nb = cur ^ 1;

        float xp0 = 0.f, xp1 = 0.f;
        if (tid < 256) {
            const float* xpt = g_xp + (size_t)t * (BATCH * HID);
            xp0 = xpt[(size_t)b0 * HID + jg];
            xp1 = xpt[(size_t)(b0 + 1) * HID + jg];
        }

        if (t > 0) {
            const uint32_t parity = (uint32_t)(((t - 1) >> 1) & 1);
            const uint32_t mb = mywait + (uint32_t)(cur * 64);
            bar_wait_cta(mb, parity);
            if ((ksl & 1) == 0 && c2 == 0) {
                asm volatile("mbarrier.arrive.expect_tx.shared.b64 _, [%0], %1;"
                             :: "r"(mb), "r"(SLICE_TXB) : "memory");
            }
        }

        const ull* hc = (const ull*)(hb + cur * 4096) + (size_t)ksl * 32 * 4;
        ull a00=0, a01=0, a10=0, a11=0, a20=0, a21=0, a30=0, a31=0;
#pragma unroll 8
        for (int kk = 0; kk < 32; kk++) {
            const float2 w = *(const float2*)(wp + kk * 64);
            const ulonglong2 h01 = *(const ulonglong2*)(hc + kk * 4);
            const ulonglong2 h23 = *(const ulonglong2*)(hc + kk * 4 + 2);
            const ull w0 = dup2(w.x), w1 = dup2(w.y);
            fma2(a00, h01.x, w0); fma2(a01, h01.y, w0);
            fma2(a10, h23.x, w0); fma2(a11, h23.y, w0);
            fma2(a20, h01.x, w1); fma2(a21, h01.y, w1);
            fma2(a30, h23.x, w1); fma2(a31, h23.y, w1);
        }
        {   // partials -> red[pair][ksl][col]; per pair, cols (2c2, 2c2+1)
            //   a00:pair0,col0  a01:pair1,col0  a10:pair2,col0  a11:pair3,col0
            //   a20:pair0,col1  a21:pair1,col1  a30:pair2,col1  a31:pair3,col1
            ulonglong2 v;
            v.x = a00; v.y = a20;
            *(ulonglong2*)&red[(0 * 16 + ksl) * 64 + 2 * c2] = v;
            v.x = a01; v.y = a21;
            *(ulonglong2*)&red[(1 * 16 + ksl) * 64 + 2 * c2] = v;
            v.x = a10; v.y = a30;
            *(ulonglong2*)&red[(2 * 16 + ksl) * 64 + 2 * c2] = v;
            v.x = a11; v.y = a31;
            *(ulonglong2*)&red[(3 * 16 + ksl) * 64 + 2 * c2] = v;
        }
        __syncthreads();   // sync1: all partials visible

        if (tid < 256) {
            // reduce 16 k-slices for (pair rp, col c) — lane-contiguous loads
            const ull* rbase = red + (size_t)rp * (16 * 64) + c;
            ull s[8];
#pragma unroll
            for (int i = 0; i < 8; i++)
                s[i] = add2v(rbase[(size_t)(2 * i) * 64], rbase[(size_t)(2 * i + 1) * 64]);
            s[0] = add2v(s[0], s[1]); s[2] = add2v(s[2], s[3]);
            s[4] = add2v(s[4], s[5]); s[6] = add2v(s[6], s[7]);
            s[0] = add2v(s[0], s[2]); s[4] = add2v(s[4], s[6]);
            s[0] = add2v(s[0], s[4]);
            float lo, hi; unpack2(s[0], lo, hi);
            const float v0 = fast_tanh(lo + xp0);
            const float v1 = fast_tanh(hi + xp1);
            stg[(size_t)nb * 256 + c * 4 + rp] = pack2(v0, v1);
        }
        __syncthreads();   // sync2: staging complete; red free for t+1

        if (tid == 0) {
            asm volatile("fence.proxy.async.shared::cta;" ::: "memory");
            const uint32_t src  = stg_u32 + (uint32_t)(nb * 2048);
            const uint32_t doff = (uint32_t)(nb * 16384);
            const uint32_t boff = (uint32_t)(nb * 64);
#pragma unroll
            for (int r = 0; r < 8; r++) {
                asm volatile(
                    "cp.async.bulk.shared::cluster.shared::cta.mbarrier::complete_tx::bytes "
                    "[%0], [%1], %2, [%3];"
                    :: "r"(pdst[r] + doff), "r"(src), "r"(SLICE_TXB), "r"(pbar[r] + boff)
                    : "memory");
            }
        }
    }

    bar_wait_cta(mywait, 1u);
    __syncthreads();
    if (tid < 256) {
        const float2 hv = *(const float2*)&hb[jg * 8 + 2 * rp];
        out[(size_t)b0 * HID + jg]       = hv.x;
        out[(size_t)(b0 + 1) * HID + jg] = hv.y;
    }

    asm volatile("barrier.cluster.arrive.aligned;" ::: "memory");
    asm volatile("barrier.cluster.wait.aligned;"   ::: "memory");
}

// ============================================================
extern "C" void kernel_launch(void* const* d_in, const int* in_sizes, int n_in,
                              void* d_out, int out_size)
{
    (void)in_sizes; (void)n_in; (void)out_size;
    const float* x    = (const float*)d_in[0];
    const float* Wx   = (const float*)d_in[1];
    const float* Wh   = (const float*)d_in[2];
    const float* bias = (const float*)d_in[3];
    float* out = (float*)d_out;

    cudaFuncSetAttribute(rnn_scan, cudaFuncAttributeMaxDynamicSharedMemorySize, SMEM_SCAN8);

    dim3 g1(4, 1024);
    xp_gemm<<<g1, 256>>>(x, Wx, bias);
    rnn_scan<<<128, 512, SMEM_SCAN8>>>(Wh, out);
}